// round 1
// baseline (speedup 1.0000x reference)
#include <cuda_runtime.h>
#include <math.h>

#define MEM_DIM 1024
#define N_CHILD 16384

#define BM 128
#define BN 64
#define BK 32
#define TM 8
#define TN 4
// threads = (BM/TM) * (BN/TN) = 16 * 16 = 256

// Scratch (no cudaMalloc allowed)
__device__ float g_gates[3 * MEM_DIM];  // [i | o | u] activated gate values
__device__ float g_fcsum[MEM_DIM];      // sum over children of f ⊙ child_c

// ---------------------------------------------------------------------------
// Packed f32x2 helpers (Blackwell sm_100+ PTX; doubles FFMA throughput)
// ---------------------------------------------------------------------------
__device__ __forceinline__ unsigned long long pack2(float lo, float hi) {
    unsigned long long r;
    asm("mov.b64 %0, {%1, %2};" : "=l"(r) : "f"(lo), "f"(hi));
    return r;
}
__device__ __forceinline__ void unpack2(unsigned long long v, float& lo, float& hi) {
    asm("mov.b64 {%0, %1}, %2;" : "=f"(lo), "=f"(hi) : "l"(v));
}
__device__ __forceinline__ void fma2(unsigned long long& d,
                                     unsigned long long a,
                                     unsigned long long b) {
    asm("fma.rn.f32x2 %0, %1, %2, %0;" : "+l"(d) : "l"(a), "l"(b));
}

__device__ __forceinline__ float sigmoidf_(float x) {
    return 1.0f / (1.0f + __expf(-x));
}

// ---------------------------------------------------------------------------
// Kernel 1: gate matvecs on child_h_sum (i, o, u) + zero the fc accumulator.
// One warp per (gate, output row). 3 * 1024 = 3072 warps.
// ---------------------------------------------------------------------------
__global__ void gates_kernel(const float* __restrict__ hsum,
                             const float* __restrict__ W_ih, const float* __restrict__ b_ih,
                             const float* __restrict__ W_uh, const float* __restrict__ b_uh,
                             const float* __restrict__ W_oh, const float* __restrict__ b_oh) {
    if (blockIdx.x == 0) {
        for (int j = threadIdx.x; j < MEM_DIM; j += blockDim.x) g_fcsum[j] = 0.0f;
    }
    int warp = (blockIdx.x * blockDim.x + threadIdx.x) >> 5;
    int lane = threadIdx.x & 31;
    if (warp >= 3 * MEM_DIM) return;
    int gate = warp / MEM_DIM;   // 0=i, 1=o, 2=u
    int row  = warp % MEM_DIM;

    const float* W = (gate == 0) ? W_ih : ((gate == 1) ? W_oh : W_uh);
    const float* b = (gate == 0) ? b_ih : ((gate == 1) ? b_oh : b_uh);

    const float4* h4 = (const float4*)hsum;
    const float4* w4 = (const float4*)(W + (size_t)row * MEM_DIM);

    float s = 0.0f;
#pragma unroll
    for (int idx = 0; idx < MEM_DIM / 4 / 32; idx++) {
        float4 hv = h4[lane + idx * 32];
        float4 wv = w4[lane + idx * 32];
        s += hv.x * wv.x + hv.y * wv.y + hv.z * wv.z + hv.w * wv.w;
    }
#pragma unroll
    for (int off = 16; off > 0; off >>= 1) s += __shfl_xor_sync(0xffffffffu, s, off);

    if (lane == 0) {
        float pre = s + b[row];
        g_gates[gate * MEM_DIM + row] = (gate == 2) ? tanhf(pre) : 1.0f / (1.0f + expf(-pre));
    }
}

// ---------------------------------------------------------------------------
// Kernel 2: fused  sum_n sigmoid(child_h @ W_fh.T + b_fh) ⊙ child_c
// Tiled fp32 GEMM with f32x2-packed accumulators (pairs along M).
// Grid: (MEM_DIM/BN, N_CHILD/BM). Block: 256 threads.
// ---------------------------------------------------------------------------
__global__ void __launch_bounds__(256)
fgemm_kernel(const float* __restrict__ child_h,   // [N_CHILD, MEM_DIM]
             const float* __restrict__ child_c,   // [N_CHILD, MEM_DIM]
             const float* __restrict__ W_fh,      // [MEM_DIM, MEM_DIM]
             const float* __restrict__ b_fh) {
    __shared__ float As[BK][BM];        // A transposed: As[k][m]
    __shared__ float Bs[BK][BN];        // B transposed: Bs[k][n]
    __shared__ float red[BN][16];       // column partials per tidm group

    const int tid  = threadIdx.x;
    const int tidn = tid & 15;          // 0..15 -> output cols tidn*TN .. +3
    const int tidm = tid >> 4;          // 0..15 -> rows tidm*TM .. +7
    const int m0   = blockIdx.y * BM;
    const int n0   = blockIdx.x * BN;

    // acc2[ip][j]: packed pair of M-rows (2*ip, 2*ip+1) for output col j
    unsigned long long acc2[TM / 2][TN];
#pragma unroll
    for (int ip = 0; ip < TM / 2; ip++)
#pragma unroll
        for (int j = 0; j < TN; j++) acc2[ip][j] = 0ull;

    for (int k0 = 0; k0 < MEM_DIM; k0 += BK) {
        // Load A tile: BM x BK = 1024 float4s, 4 per thread, store transposed
#pragma unroll
        for (int l = 0; l < 4; l++) {
            int idx = tid + l * 256;
            int row = idx >> 3;
            int c4  = idx & 7;
            float4 v = *(const float4*)(child_h + (size_t)(m0 + row) * MEM_DIM + k0 + c4 * 4);
            As[c4 * 4 + 0][row] = v.x;
            As[c4 * 4 + 1][row] = v.y;
            As[c4 * 4 + 2][row] = v.z;
            As[c4 * 4 + 3][row] = v.w;
        }
        // Load B tile: BN x BK = 512 float4s, 2 per thread, store transposed
#pragma unroll
        for (int l = 0; l < 2; l++) {
            int idx = tid + l * 256;
            int row = idx >> 3;
            int c4  = idx & 7;
            float4 v = *(const float4*)(W_fh + (size_t)(n0 + row) * MEM_DIM + k0 + c4 * 4);
            Bs[c4 * 4 + 0][row] = v.x;
            Bs[c4 * 4 + 1][row] = v.y;
            Bs[c4 * 4 + 2][row] = v.z;
            Bs[c4 * 4 + 3][row] = v.w;
        }
        __syncthreads();

#pragma unroll
        for (int kk = 0; kk < BK; kk++) {
            // A fragment: 4 packed pairs along M (LDS.64, no pack needed)
            unsigned long long a2[TM / 2];
#pragma unroll
            for (int ip = 0; ip < TM / 2; ip++)
                a2[ip] = *(const unsigned long long*)&As[kk][tidm * TM + 2 * ip];
            // B fragment: one float4, broadcast-packed per column
            float4 bf = *(const float4*)&Bs[kk][tidn * TN];
            unsigned long long b2[TN];
            b2[0] = pack2(bf.x, bf.x);
            b2[1] = pack2(bf.y, bf.y);
            b2[2] = pack2(bf.z, bf.z);
            b2[3] = pack2(bf.w, bf.w);
#pragma unroll
            for (int ip = 0; ip < TM / 2; ip++)
#pragma unroll
                for (int j = 0; j < TN; j++) fma2(acc2[ip][j], a2[ip], b2[j]);
        }
        __syncthreads();
    }

    // Epilogue: f = sigmoid(y + b), fc = f * child_c, reduce over M-rows
    float bb[TN];
#pragma unroll
    for (int j = 0; j < TN; j++) bb[j] = b_fh[n0 + tidn * TN + j];

    float colsum[TN] = {0.f, 0.f, 0.f, 0.f};
#pragma unroll
    for (int ip = 0; ip < TM / 2; ip++) {
        int mA = m0 + tidm * TM + 2 * ip;
        float4 c0 = *(const float4*)(child_c + (size_t)mA * MEM_DIM + n0 + tidn * TN);
        float4 c1 = *(const float4*)(child_c + (size_t)(mA + 1) * MEM_DIM + n0 + tidn * TN);
        float cc0[4] = {c0.x, c0.y, c0.z, c0.w};
        float cc1[4] = {c1.x, c1.y, c1.z, c1.w};
#pragma unroll
        for (int j = 0; j < TN; j++) {
            float y0, y1;
            unpack2(acc2[ip][j], y0, y1);
            colsum[j] += sigmoidf_(y0 + bb[j]) * cc0[j];
            colsum[j] += sigmoidf_(y1 + bb[j]) * cc1[j];
        }
    }

    // Intra-block column reduction (over the 16 tidm groups), then one atomic
    // per output column per block.
#pragma unroll
    for (int j = 0; j < TN; j++) red[tidn * TN + j][tidm] = colsum[j];
    __syncthreads();
    if (tid < BN) {
        float s = 0.0f;
#pragma unroll
        for (int i = 0; i < 16; i++) s += red[tid][i];
        atomicAdd(&g_fcsum[n0 + tid], s);
    }
}

// ---------------------------------------------------------------------------
// Kernel 3: c = i*u + sum(fc); h = o*tanh(c); out = [c | h]
// ---------------------------------------------------------------------------
__global__ void final_kernel(float* __restrict__ out) {
    int j = blockIdx.x * blockDim.x + threadIdx.x;
    if (j < MEM_DIM) {
        float gi = g_gates[j];
        float go = g_gates[MEM_DIM + j];
        float gu = g_gates[2 * MEM_DIM + j];
        float c  = gi * gu + g_fcsum[j];
        out[j]            = c;
        out[MEM_DIM + j]  = go * tanhf(c);
    }
}

// ---------------------------------------------------------------------------
extern "C" void kernel_launch(void* const* d_in, const int* in_sizes, int n_in,
                              void* d_out, int out_size) {
    const float* child_c = (const float*)d_in[0];
    const float* child_h = (const float*)d_in[1];
    const float* hsum    = (const float*)d_in[2];
    const float* W_ih    = (const float*)d_in[3];
    const float* b_ih    = (const float*)d_in[4];
    const float* W_fh    = (const float*)d_in[5];
    const float* b_fh    = (const float*)d_in[6];
    const float* W_uh    = (const float*)d_in[7];
    const float* b_uh    = (const float*)d_in[8];
    const float* W_oh    = (const float*)d_in[9];
    const float* b_oh    = (const float*)d_in[10];

    // 3072 warps for gates -> 384 blocks of 256 threads
    gates_kernel<<<384, 256>>>(hsum, W_ih, b_ih, W_uh, b_uh, W_oh, b_oh);

    dim3 grid(MEM_DIM / BN, N_CHILD / BM);  // (16, 128)
    fgemm_kernel<<<grid, 256>>>(child_h, child_c, W_fh, b_fh);

    final_kernel<<<1, MEM_DIM>>>((float*)d_out);
}

// round 2
// speedup vs baseline: 3.2663x; 3.2663x over previous
#include <cuda_runtime.h>
#include <math.h>
#include <stdint.h>

#define MEM_DIM 1024
#define N_CHILD 16384

#define BM 128
#define BN 128
#define BK 16
#define THREADS 256
#define KITERS (MEM_DIM / BK)       // 64
#define LDSS (BK + 4)               // 20 floats = 80B row stride: 16B-aligned, conflict-free

__device__ float g_gates[3 * MEM_DIM];  // [i | o | u]
__device__ float g_fcsum[MEM_DIM];

// ---------------------------------------------------------------------------
__device__ __forceinline__ uint32_t cvt_tf32(float x) {
    uint32_t r; asm("cvt.rna.tf32.f32 %0, %1;" : "=r"(r) : "f"(x)); return r;
}
__device__ __forceinline__ void mma_tf32(float* d, const uint32_t* a, const uint32_t* b) {
    asm volatile(
        "mma.sync.aligned.m16n8k8.row.col.f32.tf32.tf32.f32 "
        "{%0,%1,%2,%3}, {%4,%5,%6,%7}, {%8,%9}, {%0,%1,%2,%3};\n"
        : "+f"(d[0]), "+f"(d[1]), "+f"(d[2]), "+f"(d[3])
        : "r"(a[0]), "r"(a[1]), "r"(a[2]), "r"(a[3]), "r"(b[0]), "r"(b[1]));
}
__device__ __forceinline__ void cpa16(uint32_t s, const void* g) {
    asm volatile("cp.async.cg.shared.global [%0], [%1], 16;\n" :: "r"(s), "l"(g));
}
__device__ __forceinline__ float sigmoidf_(float x) {
    return 1.0f / (1.0f + __expf(-x));
}

// ---------------------------------------------------------------------------
// Kernel 1: gate matvecs (i, o, u) on child_h_sum + zero the fc accumulator.
// ---------------------------------------------------------------------------
__global__ void gates_kernel(const float* __restrict__ hsum,
                             const float* __restrict__ W_ih, const float* __restrict__ b_ih,
                             const float* __restrict__ W_uh, const float* __restrict__ b_uh,
                             const float* __restrict__ W_oh, const float* __restrict__ b_oh) {
    if (blockIdx.x == 0) {
        for (int j = threadIdx.x; j < MEM_DIM; j += blockDim.x) g_fcsum[j] = 0.0f;
    }
    int warp = (blockIdx.x * blockDim.x + threadIdx.x) >> 5;
    int lane = threadIdx.x & 31;
    if (warp >= 3 * MEM_DIM) return;
    int gate = warp / MEM_DIM;   // 0=i, 1=o, 2=u
    int row  = warp % MEM_DIM;

    const float* W = (gate == 0) ? W_ih : ((gate == 1) ? W_oh : W_uh);
    const float* b = (gate == 0) ? b_ih : ((gate == 1) ? b_oh : b_uh);

    const float4* h4 = (const float4*)hsum;
    const float4* w4 = (const float4*)(W + (size_t)row * MEM_DIM);

    float s = 0.0f;
#pragma unroll
    for (int idx = 0; idx < MEM_DIM / 4 / 32; idx++) {
        float4 hv = h4[lane + idx * 32];
        float4 wv = w4[lane + idx * 32];
        s += hv.x * wv.x + hv.y * wv.y + hv.z * wv.z + hv.w * wv.w;
    }
#pragma unroll
    for (int off = 16; off > 0; off >>= 1) s += __shfl_xor_sync(0xffffffffu, s, off);

    if (lane == 0) {
        float pre = s + b[row];
        g_gates[gate * MEM_DIM + row] = (gate == 2) ? tanhf(pre) : 1.0f / (1.0f + expf(-pre));
    }
}

// ---------------------------------------------------------------------------
// Kernel 2: sum_n sigmoid(child_h @ W_fh.T + b_fh) ⊙ child_c
// tf32 tensor-core GEMM (mma.m16n8k8) with fused epilogue + column reduction.
// Block 128x128x16, 8 warps (2 M x 4 N), warp tile 64x32, cp.async double-buffer.
// ---------------------------------------------------------------------------
__global__ void __launch_bounds__(THREADS)
fgemm_kernel(const float* __restrict__ child_h,   // [N_CHILD, MEM_DIM]
             const float* __restrict__ child_c,   // [N_CHILD, MEM_DIM]
             const float* __restrict__ W_fh,      // [MEM_DIM, MEM_DIM]
             const float* __restrict__ b_fh) {
    __shared__ float As[2][BM][LDSS];
    __shared__ float Bs[2][BN][LDSS];
    __shared__ float red[2][BN];

    const int tid  = threadIdx.x;
    const int lane = tid & 31;
    const int warp = tid >> 5;
    const int wm   = warp & 1;      // 0..1  -> 64 rows each
    const int wn   = warp >> 1;     // 0..3  -> 32 cols each
    const int g    = lane >> 2;     // 0..7
    const int t    = lane & 3;      // 0..3
    const int m0   = blockIdx.y * BM;
    const int n0   = blockIdx.x * BN;

    float acc[4][4][4];
#pragma unroll
    for (int mt = 0; mt < 4; mt++)
#pragma unroll
        for (int nt = 0; nt < 4; nt++)
#pragma unroll
            for (int r = 0; r < 4; r++) acc[mt][nt][r] = 0.0f;

    const uint32_t sA0 = (uint32_t)__cvta_generic_to_shared(&As[0][0][0]);
    const uint32_t sB0 = (uint32_t)__cvta_generic_to_shared(&Bs[0][0][0]);
    const int BUFB = BM * LDSS * 4;   // bytes per buffer

    auto prefetch = [&](int k0, int buf) {
#pragma unroll
        for (int l = 0; l < 2; l++) {
            int idx = tid + l * 256;
            int row = idx >> 2;          // 0..127
            int c4  = idx & 3;           // float4 slot
            const float* gA = child_h + (size_t)(m0 + row) * MEM_DIM + k0 + c4 * 4;
            const float* gB = W_fh    + (size_t)(n0 + row) * MEM_DIM + k0 + c4 * 4;
            uint32_t so = (uint32_t)((row * LDSS + c4 * 4) * 4);
            cpa16(sA0 + buf * BUFB + so, gA);
            cpa16(sB0 + buf * BUFB + so, gB);
        }
    };

    prefetch(0, 0);
    asm volatile("cp.async.commit_group;\n");

    for (int it = 0; it < KITERS; it++) {
        int buf = it & 1;
        if (it + 1 < KITERS) prefetch((it + 1) * BK, buf ^ 1);
        asm volatile("cp.async.commit_group;\n");
        asm volatile("cp.async.wait_group 1;\n");
        __syncthreads();

#pragma unroll
        for (int ks = 0; ks < 2; ks++) {
            const int kk = ks * 8;
            uint32_t af[4][4], bf[4][2];
#pragma unroll
            for (int mt = 0; mt < 4; mt++) {
                int mb = wm * 64 + mt * 16;
                af[mt][0] = cvt_tf32(As[buf][mb + g    ][kk + t    ]);
                af[mt][1] = cvt_tf32(As[buf][mb + g + 8][kk + t    ]);
                af[mt][2] = cvt_tf32(As[buf][mb + g    ][kk + t + 4]);
                af[mt][3] = cvt_tf32(As[buf][mb + g + 8][kk + t + 4]);
            }
#pragma unroll
            for (int nt = 0; nt < 4; nt++) {
                int nb = wn * 32 + nt * 8;
                bf[nt][0] = cvt_tf32(Bs[buf][nb + g][kk + t    ]);
                bf[nt][1] = cvt_tf32(Bs[buf][nb + g][kk + t + 4]);
            }
#pragma unroll
            for (int mt = 0; mt < 4; mt++)
#pragma unroll
                for (int nt = 0; nt < 4; nt++)
                    mma_tf32(acc[mt][nt], af[mt], bf[nt]);
        }
        __syncthreads();
    }

    // ---- Epilogue: f = sigmoid(y + b), colsum += f * child_c ----
    float b0v[4], b1v[4];
#pragma unroll
    for (int nt = 0; nt < 4; nt++) {
        float2 bb = *(const float2*)(b_fh + n0 + wn * 32 + nt * 8 + 2 * t);
        b0v[nt] = bb.x; b1v[nt] = bb.y;
    }

    float cs0[4] = {0.f, 0.f, 0.f, 0.f};
    float cs1[4] = {0.f, 0.f, 0.f, 0.f};
#pragma unroll
    for (int mt = 0; mt < 4; mt++) {
#pragma unroll
        for (int rr = 0; rr < 2; rr++) {
            int m = m0 + wm * 64 + mt * 16 + rr * 8 + g;
            const float* crow = child_c + (size_t)m * MEM_DIM + n0;
#pragma unroll
            for (int nt = 0; nt < 4; nt++) {
                int nc = wn * 32 + nt * 8 + 2 * t;
                float2 cc = *(const float2*)(crow + nc);
                float y0 = acc[mt][nt][rr * 2 + 0] + b0v[nt];
                float y1 = acc[mt][nt][rr * 2 + 1] + b1v[nt];
                cs0[nt] += cc.x * sigmoidf_(y0);
                cs1[nt] += cc.y * sigmoidf_(y1);
            }
        }
    }

    // Reduce over the 8 row-groups (lanes differing in g): xor 4, 8, 16.
#pragma unroll
    for (int off = 4; off < 32; off <<= 1) {
#pragma unroll
        for (int nt = 0; nt < 4; nt++) {
            cs0[nt] += __shfl_xor_sync(0xffffffffu, cs0[nt], off);
            cs1[nt] += __shfl_xor_sync(0xffffffffu, cs1[nt], off);
        }
    }
    if (g == 0) {  // lanes 0..3 hold per-column sums for this warp
#pragma unroll
        for (int nt = 0; nt < 4; nt++) {
            int nc = wn * 32 + nt * 8 + 2 * t;
            red[wm][nc]     = cs0[nt];
            red[wm][nc + 1] = cs1[nt];
        }
    }
    __syncthreads();
    if (tid < BN) {
        atomicAdd(&g_fcsum[n0 + tid], red[0][tid] + red[1][tid]);
    }
}

// ---------------------------------------------------------------------------
// Kernel 3: c = i*u + sum(fc); h = o*tanh(c); out = [c | h]
// ---------------------------------------------------------------------------
__global__ void final_kernel(float* __restrict__ out) {
    int j = blockIdx.x * blockDim.x + threadIdx.x;
    if (j < MEM_DIM) {
        float gi = g_gates[j];
        float go = g_gates[MEM_DIM + j];
        float gu = g_gates[2 * MEM_DIM + j];
        float c  = gi * gu + g_fcsum[j];
        out[j]           = c;
        out[MEM_DIM + j] = go * tanhf(c);
    }
}

// ---------------------------------------------------------------------------
extern "C" void kernel_launch(void* const* d_in, const int* in_sizes, int n_in,
                              void* d_out, int out_size) {
    const float* child_c = (const float*)d_in[0];
    const float* child_h = (const float*)d_in[1];
    const float* hsum    = (const float*)d_in[2];
    const float* W_ih    = (const float*)d_in[3];
    const float* b_ih    = (const float*)d_in[4];
    const float* W_fh    = (const float*)d_in[5];
    const float* b_fh    = (const float*)d_in[6];
    const float* W_uh    = (const float*)d_in[7];
    const float* b_uh    = (const float*)d_in[8];
    const float* W_oh    = (const float*)d_in[9];
    const float* b_oh    = (const float*)d_in[10];

    gates_kernel<<<384, 256>>>(hsum, W_ih, b_ih, W_uh, b_uh, W_oh, b_oh);

    dim3 grid(MEM_DIM / BN, N_CHILD / BM);   // (8, 128)
    fgemm_kernel<<<grid, THREADS>>>(child_h, child_c, W_fh, b_fh);

    final_kernel<<<1, MEM_DIM>>>((float*)d_out);
}

// round 5
// speedup vs baseline: 5.2189x; 1.5978x over previous
#include <cuda_runtime.h>
#include <cuda_fp16.h>
#include <math.h>
#include <stdint.h>

#define MEM_DIM 1024
#define N_CHILD 16384

#define BM 128
#define BN 128
#define BKH 32                     // K halves per pipeline stage
#define KITERS (MEM_DIM / BKH)     // 32
#define SAH 40                     // padded row stride in halves (80B)
#define THREADS 256

// ---- device scratch (no cudaMalloc allowed) ----
__device__ float  g_gates[3 * MEM_DIM];
__device__ float  g_fcsum[MEM_DIM];
__device__ __half g_h_h[(size_t)N_CHILD * MEM_DIM];   // fp16 child_h
__device__ __half g_w_h[(size_t)MEM_DIM * MEM_DIM];   // fp16 W_fh

// ---------------------------------------------------------------------------
__device__ __forceinline__ void ldm_x4(uint32_t* r, uint32_t addr) {
    asm volatile("ldmatrix.sync.aligned.m8n8.x4.shared.b16 {%0,%1,%2,%3}, [%4];"
                 : "=r"(r[0]), "=r"(r[1]), "=r"(r[2]), "=r"(r[3]) : "r"(addr));
}
__device__ __forceinline__ void mma_f16(float* d, const uint32_t* a, const uint32_t* b) {
    asm volatile(
        "mma.sync.aligned.m16n8k16.row.col.f32.f16.f16.f32 "
        "{%0,%1,%2,%3}, {%4,%5,%6,%7}, {%8,%9}, {%0,%1,%2,%3};\n"
        : "+f"(d[0]), "+f"(d[1]), "+f"(d[2]), "+f"(d[3])
        : "r"(a[0]), "r"(a[1]), "r"(a[2]), "r"(a[3]), "r"(b[0]), "r"(b[1]));
}
__device__ __forceinline__ void cpa16(uint32_t s, const void* g) {
    asm volatile("cp.async.cg.shared.global [%0], [%1], 16;\n" :: "r"(s), "l"(g));
}
__device__ __forceinline__ float sigmoidf_(float x) {
    return 1.0f / (1.0f + __expf(-x));
}

// ---------------------------------------------------------------------------
// Prep: convert child_h and W_fh to fp16 scratch.
// ---------------------------------------------------------------------------
__global__ void prep_half(const float* __restrict__ h, const float* __restrict__ w) {
    const int64_t NH = (int64_t)N_CHILD * MEM_DIM / 4;
    const int64_t NW = (int64_t)MEM_DIM * MEM_DIM / 4;
    int64_t i0 = (int64_t)blockIdx.x * blockDim.x + threadIdx.x;
    int64_t stride = (int64_t)gridDim.x * blockDim.x;
    const float4* h4 = (const float4*)h;
    __half2* ho = (__half2*)g_h_h;
    for (int64_t k = i0; k < NH; k += stride) {
        float4 v = h4[k];
        ho[2 * k]     = __floats2half2_rn(v.x, v.y);
        ho[2 * k + 1] = __floats2half2_rn(v.z, v.w);
    }
    const float4* w4 = (const float4*)w;
    __half2* wo = (__half2*)g_w_h;
    for (int64_t k = i0; k < NW; k += stride) {
        float4 v = w4[k];
        wo[2 * k]     = __floats2half2_rn(v.x, v.y);
        wo[2 * k + 1] = __floats2half2_rn(v.z, v.w);
    }
}

// ---------------------------------------------------------------------------
// Gates: i,o,u matvecs on child_h_sum + zero the fc accumulator.
// ---------------------------------------------------------------------------
__global__ void gates_kernel(const float* __restrict__ hsum,
                             const float* __restrict__ W_ih, const float* __restrict__ b_ih,
                             const float* __restrict__ W_uh, const float* __restrict__ b_uh,
                             const float* __restrict__ W_oh, const float* __restrict__ b_oh) {
    if (blockIdx.x == 0) {
        for (int j = threadIdx.x; j < MEM_DIM; j += blockDim.x) g_fcsum[j] = 0.0f;
    }
    int warp = (blockIdx.x * blockDim.x + threadIdx.x) >> 5;
    int lane = threadIdx.x & 31;
    if (warp >= 3 * MEM_DIM) return;
    int gate = warp / MEM_DIM;
    int row  = warp % MEM_DIM;
    const float* W = (gate == 0) ? W_ih : ((gate == 1) ? W_oh : W_uh);
    const float* b = (gate == 0) ? b_ih : ((gate == 1) ? b_oh : b_uh);
    const float4* h4 = (const float4*)hsum;
    const float4* w4 = (const float4*)(W + (size_t)row * MEM_DIM);
    float s = 0.0f;
#pragma unroll
    for (int idx = 0; idx < MEM_DIM / 128; idx++) {
        float4 hv = h4[lane + idx * 32];
        float4 wv = w4[lane + idx * 32];
        s += hv.x * wv.x + hv.y * wv.y + hv.z * wv.z + hv.w * wv.w;
    }
#pragma unroll
    for (int off = 16; off > 0; off >>= 1) s += __shfl_xor_sync(0xffffffffu, s, off);
    if (lane == 0) {
        float pre = s + b[row];
        g_gates[gate * MEM_DIM + row] = (gate == 2) ? tanhf(pre) : 1.0f / (1.0f + expf(-pre));
    }
}

// ---------------------------------------------------------------------------
// Main GEMM: sum_n sigmoid(child_h @ W_fh.T + b_fh) ⊙ child_c
// fp16 mma.m16n8k16, ldmatrix fragments, cp.async double-buffer.
// Block tile 128x128x32, 8 warps (2 M x 4 N), warp tile 64x32.
// ---------------------------------------------------------------------------
__global__ void __launch_bounds__(THREADS, 2)
fgemm_kernel(const float* __restrict__ child_c,
             const float* __restrict__ b_fh) {
    __shared__ __half As[2][BM][SAH];
    __shared__ __half Bs[2][BN][SAH];
    __shared__ float  red[2][BN];

    const int tid  = threadIdx.x;
    const int lane = tid & 31;
    const int warp = tid >> 5;
    const int wm   = warp & 1;      // 0..1 -> 64 rows each
    const int wn   = warp >> 1;     // 0..3 -> 32 cols each
    const int g    = lane >> 2;     // 0..7
    const int t    = lane & 3;      // 0..3
    const int m0   = blockIdx.y * BM;
    const int n0   = blockIdx.x * BN;

    float acc[4][4][4];
#pragma unroll
    for (int mt = 0; mt < 4; mt++)
#pragma unroll
        for (int nt = 0; nt < 4; nt++)
#pragma unroll
            for (int r = 0; r < 4; r++) acc[mt][nt][r] = 0.0f;

    const uint32_t sA = (uint32_t)__cvta_generic_to_shared(&As[0][0][0]);
    const uint32_t sB = (uint32_t)__cvta_generic_to_shared(&Bs[0][0][0]);
    const uint32_t BUFB = BM * SAH * 2;   // bytes per buffer

    const __half* gH = g_h_h + (size_t)m0 * MEM_DIM;
    const __half* gW = g_w_h + (size_t)n0 * MEM_DIM;

    auto prefetch = [&](int k0, int buf) {
#pragma unroll
        for (int l = 0; l < 2; l++) {
            int idx = tid + l * 256;
            int row = idx >> 2;          // 0..127
            int c   = idx & 3;           // 16B chunk (8 halves)
            uint32_t so = (uint32_t)buf * BUFB + (uint32_t)(row * SAH + c * 8) * 2;
            cpa16(sA + so, gH + (size_t)row * MEM_DIM + k0 + c * 8);
            cpa16(sB + so, gW + (size_t)row * MEM_DIM + k0 + c * 8);
        }
    };

    // ldmatrix lane-address components
    const int q  = lane >> 3;            // 0..3
    const int r8 = lane & 7;             // 0..7
    const int a_row = wm * 64 + (q & 1) * 8 + r8;       // + mt*16
    const int a_col = (q >> 1) * 8;                     // + kk
    const int b_row = wn * 32 + (q >> 1) * 8 + r8;      // + p*16
    const int b_col = (q & 1) * 8;                      // + kk

    prefetch(0, 0);
    asm volatile("cp.async.commit_group;\n");

    for (int it = 0; it < KITERS; it++) {
        int buf = it & 1;
        if (it + 1 < KITERS) prefetch((it + 1) * BKH, buf ^ 1);
        asm volatile("cp.async.commit_group;\n");
        asm volatile("cp.async.wait_group 1;\n");
        __syncthreads();

        uint32_t baseA = sA + buf * BUFB;
        uint32_t baseB = sB + buf * BUFB;
#pragma unroll
        for (int ks = 0; ks < 2; ks++) {
            const int kk = ks * 16;
            uint32_t af[4][4], bf[2][4];
#pragma unroll
            for (int mt = 0; mt < 4; mt++)
                ldm_x4(af[mt], baseA + ((a_row + mt * 16) * SAH + a_col + kk) * 2);
#pragma unroll
            for (int p = 0; p < 2; p++)
                ldm_x4(bf[p], baseB + ((b_row + p * 16) * SAH + b_col + kk) * 2);
#pragma unroll
            for (int mt = 0; mt < 4; mt++)
#pragma unroll
                for (int nt = 0; nt < 4; nt++)
                    mma_f16(acc[mt][nt], af[mt], &bf[nt >> 1][(nt & 1) * 2]);
        }
        __syncthreads();
    }

    // ---- Epilogue: f = sigmoid(y + b), colsum += f * child_c ----
    float b0v[4], b1v[4];
#pragma unroll
    for (int nt = 0; nt < 4; nt++) {
        float2 bb = *(const float2*)(b_fh + n0 + wn * 32 + nt * 8 + 2 * t);
        b0v[nt] = bb.x; b1v[nt] = bb.y;
    }

    float cs0[4] = {0.f, 0.f, 0.f, 0.f};
    float cs1[4] = {0.f, 0.f, 0.f, 0.f};
#pragma unroll
    for (int mt = 0; mt < 4; mt++) {
#pragma unroll
        for (int rr = 0; rr < 2; rr++) {
            int m = m0 + wm * 64 + mt * 16 + rr * 8 + g;
            const float* crow = child_c + (size_t)m * MEM_DIM + n0;
#pragma unroll
            for (int nt = 0; nt < 4; nt++) {
                int nc = wn * 32 + nt * 8 + 2 * t;
                float2 cc = *(const float2*)(crow + nc);
                float y0 = acc[mt][nt][rr * 2 + 0] + b0v[nt];
                float y1 = acc[mt][nt][rr * 2 + 1] + b1v[nt];
                cs0[nt] += cc.x * sigmoidf_(y0);
                cs1[nt] += cc.y * sigmoidf_(y1);
            }
        }
    }

    // Reduce over the 8 row-groups (lanes differing in g): xor 4, 8, 16.
#pragma unroll
    for (int off = 4; off < 32; off <<= 1) {
#pragma unroll
        for (int nt = 0; nt < 4; nt++) {
            cs0[nt] += __shfl_xor_sync(0xffffffffu, cs0[nt], off);
            cs1[nt] += __shfl_xor_sync(0xffffffffu, cs1[nt], off);
        }
    }
    if (g == 0) {  // lanes 0..3 hold per-column sums for this warp
#pragma unroll
        for (int nt = 0; nt < 4; nt++) {
            int nc = wn * 32 + nt * 8 + 2 * t;
            red[wm][nc]     = cs0[nt];
            red[wm][nc + 1] = cs1[nt];
        }
    }
    __syncthreads();
    if (tid < BN) {
        atomicAdd(&g_fcsum[n0 + tid], red[0][tid] + red[1][tid]);
    }
}

// ---------------------------------------------------------------------------
// Final: c = i*u + sum(fc); h = o*tanh(c); out = [c | h]
// ---------------------------------------------------------------------------
__global__ void final_kernel(float* __restrict__ out) {
    int j = blockIdx.x * blockDim.x + threadIdx.x;
    if (j < MEM_DIM) {
        float gi = g_gates[j];
        float go = g_gates[MEM_DIM + j];
        float gu = g_gates[2 * MEM_DIM + j];
        float c  = gi * gu + g_fcsum[j];
        out[j]           = c;
        out[MEM_DIM + j] = go * tanhf(c);
    }
}

// ---------------------------------------------------------------------------
extern "C" void kernel_launch(void* const* d_in, const int* in_sizes, int n_in,
                              void* d_out, int out_size) {
    const float* child_c = (const float*)d_in[0];
    const float* child_h = (const float*)d_in[1];
    const float* hsum    = (const float*)d_in[2];
    const float* W_ih    = (const float*)d_in[3];
    const float* b_ih    = (const float*)d_in[4];
    const float* W_fh    = (const float*)d_in[5];
    const float* b_fh    = (const float*)d_in[6];
    const float* W_uh    = (const float*)d_in[7];
    const float* b_uh    = (const float*)d_in[8];
    const float* W_oh    = (const float*)d_in[9];
    const float* b_oh    = (const float*)d_in[10];

    prep_half<<<2048, 256>>>(child_h, W_fh);
    gates_kernel<<<384, 256>>>(hsum, W_ih, b_ih, W_uh, b_uh, W_oh, b_oh);

    dim3 grid(MEM_DIM / BN, N_CHILD / BM);   // (8, 128)
    fgemm_kernel<<<grid, THREADS>>>(child_c, b_fh);

    final_kernel<<<1, MEM_DIM>>>((float*)d_out);
}

// round 6
// speedup vs baseline: 5.4405x; 1.0425x over previous
#include <cuda_runtime.h>
#include <cuda_fp16.h>
#include <math.h>
#include <stdint.h>

#define MEM_DIM 1024
#define N_CHILD 16384

#define BM 128
#define BN 128
#define BKH 32                     // K halves per pipeline stage
#define KITERS (MEM_DIM / BKH)     // 32
#define SAH 40                     // padded row stride in halves (80B)
#define THREADS 256
#define NSTAGE 3
#define STAGE_BYTES 20480          // (A 10240 + B 10240) per stage
#define RED_OFF (NSTAGE * STAGE_BYTES)          // 61440
#define FLAG_OFF (RED_OFF + 2 * BN * 4)         // 62464
#define SMEM_TOTAL (FLAG_OFF + 16)              // 62480
#define GRID_TOTAL ((MEM_DIM / BN) * (N_CHILD / BM))  // 1024

// ---- device scratch (no cudaMalloc allowed) ----
__device__ float  g_gates[3 * MEM_DIM];
__device__ float  g_fcsum[MEM_DIM];
__device__ unsigned int g_done;
__device__ __half g_h_h[(size_t)N_CHILD * MEM_DIM];   // fp16 child_h
__device__ __half g_w_h[(size_t)MEM_DIM * MEM_DIM];   // fp16 W_fh

// ---------------------------------------------------------------------------
__device__ __forceinline__ void ldm_x4(uint32_t* r, uint32_t addr) {
    asm volatile("ldmatrix.sync.aligned.m8n8.x4.shared.b16 {%0,%1,%2,%3}, [%4];"
                 : "=r"(r[0]), "=r"(r[1]), "=r"(r[2]), "=r"(r[3]) : "r"(addr));
}
__device__ __forceinline__ void mma_f16(float* d, const uint32_t* a, const uint32_t* b) {
    asm volatile(
        "mma.sync.aligned.m16n8k16.row.col.f32.f16.f16.f32 "
        "{%0,%1,%2,%3}, {%4,%5,%6,%7}, {%8,%9}, {%0,%1,%2,%3};\n"
        : "+f"(d[0]), "+f"(d[1]), "+f"(d[2]), "+f"(d[3])
        : "r"(a[0]), "r"(a[1]), "r"(a[2]), "r"(a[3]), "r"(b[0]), "r"(b[1]));
}
__device__ __forceinline__ void cpa16(uint32_t s, const void* g) {
    asm volatile("cp.async.cg.shared.global [%0], [%1], 16;\n" :: "r"(s), "l"(g));
}
__device__ __forceinline__ float sigmoidf_(float x) {
    return 1.0f / (1.0f + __expf(-x));
}

// ---------------------------------------------------------------------------
// Prep + gates fused: blocks [0,384) do the i/o/u matvecs; the rest convert
// child_h / W_fh to fp16. Block 0 also zeroes g_fcsum and g_done.
// ---------------------------------------------------------------------------
#define GATE_BLOCKS 384
#define PREP_BLOCKS 2048

__global__ void prep_gates(const float* __restrict__ h, const float* __restrict__ w,
                           const float* __restrict__ hsum,
                           const float* __restrict__ W_ih, const float* __restrict__ b_ih,
                           const float* __restrict__ W_uh, const float* __restrict__ b_uh,
                           const float* __restrict__ W_oh, const float* __restrict__ b_oh) {
    if (blockIdx.x < GATE_BLOCKS) {
        if (blockIdx.x == 0) {
            for (int j = threadIdx.x; j < MEM_DIM; j += blockDim.x) g_fcsum[j] = 0.0f;
            if (threadIdx.x == 0) g_done = 0u;
        }
        int warp = (blockIdx.x * blockDim.x + threadIdx.x) >> 5;
        int lane = threadIdx.x & 31;
        if (warp >= 3 * MEM_DIM) return;
        int gate = warp / MEM_DIM;
        int row  = warp % MEM_DIM;
        const float* W = (gate == 0) ? W_ih : ((gate == 1) ? W_oh : W_uh);
        const float* b = (gate == 0) ? b_ih : ((gate == 1) ? b_oh : b_uh);
        const float4* h4 = (const float4*)hsum;
        const float4* w4 = (const float4*)(W + (size_t)row * MEM_DIM);
        float s = 0.0f;
#pragma unroll
        for (int idx = 0; idx < MEM_DIM / 128; idx++) {
            float4 hv = h4[lane + idx * 32];
            float4 wv = w4[lane + idx * 32];
            s += hv.x * wv.x + hv.y * wv.y + hv.z * wv.z + hv.w * wv.w;
        }
#pragma unroll
        for (int off = 16; off > 0; off >>= 1) s += __shfl_xor_sync(0xffffffffu, s, off);
        if (lane == 0) {
            float pre = s + b[row];
            g_gates[gate * MEM_DIM + row] = (gate == 2) ? tanhf(pre) : 1.0f / (1.0f + expf(-pre));
        }
        return;
    }

    // ---- prep section ----
    const int64_t NH = (int64_t)N_CHILD * MEM_DIM / 4;
    const int64_t NW = (int64_t)MEM_DIM * MEM_DIM / 4;
    int64_t i0 = (int64_t)(blockIdx.x - GATE_BLOCKS) * blockDim.x + threadIdx.x;
    int64_t stride = (int64_t)PREP_BLOCKS * blockDim.x;
    const float4* h4 = (const float4*)h;
    __half2* ho = (__half2*)g_h_h;
    for (int64_t k = i0; k < NH; k += stride) {
        float4 v = h4[k];
        ho[2 * k]     = __floats2half2_rn(v.x, v.y);
        ho[2 * k + 1] = __floats2half2_rn(v.z, v.w);
    }
    const float4* w4 = (const float4*)w;
    __half2* wo = (__half2*)g_w_h;
    for (int64_t k = i0; k < NW; k += stride) {
        float4 v = w4[k];
        wo[2 * k]     = __floats2half2_rn(v.x, v.y);
        wo[2 * k + 1] = __floats2half2_rn(v.z, v.w);
    }
}

// ---------------------------------------------------------------------------
// Main GEMM: sum_n sigmoid(child_h @ W_fh.T + b_fh) ⊙ child_c
// fp16 mma.m16n8k16, ldmatrix fragments, 3-stage cp.async pipeline
// (one __syncthreads per iter). Last CTA computes the final c/h output.
// ---------------------------------------------------------------------------
__global__ void __launch_bounds__(THREADS, 2)
fgemm_kernel(const float* __restrict__ child_c,
             const float* __restrict__ b_fh,
             float* __restrict__ out) {
    extern __shared__ __align__(128) uint8_t smem_raw[];
    float* red = (float*)(smem_raw + RED_OFF);              // [2][BN]
    unsigned int* flag = (unsigned int*)(smem_raw + FLAG_OFF);

    const int tid  = threadIdx.x;
    const int lane = tid & 31;
    const int warp = tid >> 5;
    const int wm   = warp & 1;      // 0..1 -> 64 rows each
    const int wn   = warp >> 1;     // 0..3 -> 32 cols each
    const int g    = lane >> 2;     // 0..7
    const int t    = lane & 3;      // 0..3
    const int m0   = blockIdx.y * BM;
    const int n0   = blockIdx.x * BN;

    float acc[4][4][4];
#pragma unroll
    for (int mt = 0; mt < 4; mt++)
#pragma unroll
        for (int nt = 0; nt < 4; nt++)
#pragma unroll
            for (int r = 0; r < 4; r++) acc[mt][nt][r] = 0.0f;

    const uint32_t sBase = (uint32_t)__cvta_generic_to_shared(smem_raw);

    const __half* gH = g_h_h + (size_t)m0 * MEM_DIM;
    const __half* gW = g_w_h + (size_t)n0 * MEM_DIM;

    auto prefetch = [&](int k0, int s) {
#pragma unroll
        for (int l = 0; l < 2; l++) {
            int idx = tid + l * 256;
            int row = idx >> 2;          // 0..127
            int c   = idx & 3;           // 16B chunk (8 halves)
            uint32_t so = sBase + (uint32_t)s * STAGE_BYTES + (uint32_t)(row * SAH + c * 8) * 2;
            cpa16(so, gH + (size_t)row * MEM_DIM + k0 + c * 8);
            cpa16(so + 10240u, gW + (size_t)row * MEM_DIM + k0 + c * 8);
        }
    };

    // ldmatrix lane-address components
    const int q  = lane >> 3;            // 0..3
    const int r8 = lane & 7;             // 0..7
    const int a_row = wm * 64 + (q & 1) * 8 + r8;       // + mt*16
    const int a_col = (q >> 1) * 8;                     // + kk
    const int b_row = wn * 32 + (q >> 1) * 8 + r8;      // + p*16
    const int b_col = (q & 1) * 8;                      // + kk

    prefetch(0, 0);
    asm volatile("cp.async.commit_group;\n");
    prefetch(BKH, 1);
    asm volatile("cp.async.commit_group;\n");

    for (int it = 0; it < KITERS; it++) {
        int s = it % NSTAGE;
        asm volatile("cp.async.wait_group 1;\n");
        __syncthreads();
        if (it + 2 < KITERS) {
            prefetch((it + 2) * BKH, (it + 2) % NSTAGE);
            asm volatile("cp.async.commit_group;\n");
        }

        uint32_t baseA = sBase + (uint32_t)s * STAGE_BYTES;
        uint32_t baseB = baseA + 10240u;
#pragma unroll
        for (int ks = 0; ks < 2; ks++) {
            const int kk = ks * 16;
            uint32_t af[4][4], bf[2][4];
#pragma unroll
            for (int mt = 0; mt < 4; mt++)
                ldm_x4(af[mt], baseA + ((a_row + mt * 16) * SAH + a_col + kk) * 2);
#pragma unroll
            for (int p = 0; p < 2; p++)
                ldm_x4(bf[p], baseB + ((b_row + p * 16) * SAH + b_col + kk) * 2);
#pragma unroll
            for (int mt = 0; mt < 4; mt++)
#pragma unroll
                for (int nt = 0; nt < 4; nt++)
                    mma_f16(acc[mt][nt], af[mt], &bf[nt >> 1][(nt & 1) * 2]);
        }
    }

    // ---- Epilogue: f = sigmoid(y + b), colsum += f * child_c ----
    float b0v[4], b1v[4];
#pragma unroll
    for (int nt = 0; nt < 4; nt++) {
        float2 bb = *(const float2*)(b_fh + n0 + wn * 32 + nt * 8 + 2 * t);
        b0v[nt] = bb.x; b1v[nt] = bb.y;
    }

    float cs0[4] = {0.f, 0.f, 0.f, 0.f};
    float cs1[4] = {0.f, 0.f, 0.f, 0.f};
#pragma unroll
    for (int mt = 0; mt < 4; mt++) {
#pragma unroll
        for (int rr = 0; rr < 2; rr++) {
            int m = m0 + wm * 64 + mt * 16 + rr * 8 + g;
            const float* crow = child_c + (size_t)m * MEM_DIM + n0;
#pragma unroll
            for (int nt = 0; nt < 4; nt++) {
                int nc = wn * 32 + nt * 8 + 2 * t;
                float2 cc = *(const float2*)(crow + nc);
                float y0 = acc[mt][nt][rr * 2 + 0] + b0v[nt];
                float y1 = acc[mt][nt][rr * 2 + 1] + b1v[nt];
                cs0[nt] += cc.x * sigmoidf_(y0);
                cs1[nt] += cc.y * sigmoidf_(y1);
            }
        }
    }

    // Reduce over the 8 row-groups (lanes differing in g): xor 4, 8, 16.
#pragma unroll
    for (int off = 4; off < 32; off <<= 1) {
#pragma unroll
        for (int nt = 0; nt < 4; nt++) {
            cs0[nt] += __shfl_xor_sync(0xffffffffu, cs0[nt], off);
            cs1[nt] += __shfl_xor_sync(0xffffffffu, cs1[nt], off);
        }
    }
    if (g == 0) {  // lanes 0..3 hold per-column sums for this warp
#pragma unroll
        for (int nt = 0; nt < 4; nt++) {
            int nc = wn * 32 + nt * 8 + 2 * t;
            red[wm * BN + nc]     = cs0[nt];
            red[wm * BN + nc + 1] = cs1[nt];
        }
    }
    __syncthreads();
    if (tid < BN) {
        atomicAdd(&g_fcsum[n0 + tid], red[tid] + red[BN + tid]);
    }

    // ---- Grid-completion: last CTA computes the final output ----
    __threadfence();
    __syncthreads();   // all 128 atomics of this CTA issued before counting
    if (tid == 0) {
        unsigned int prev = atomicAdd(&g_done, 1u);
        *flag = (prev == GRID_TOTAL - 1u);
    }
    __syncthreads();
    if (*flag) {
        __threadfence();
        for (int j = tid; j < MEM_DIM; j += THREADS) {
            float gi = g_gates[j];
            float go = g_gates[MEM_DIM + j];
            float gu = g_gates[2 * MEM_DIM + j];
            float c  = gi * gu + g_fcsum[j];
            out[j]           = c;
            out[MEM_DIM + j] = go * tanhf(c);
        }
    }
}

// ---------------------------------------------------------------------------
extern "C" void kernel_launch(void* const* d_in, const int* in_sizes, int n_in,
                              void* d_out, int out_size) {
    const float* child_c = (const float*)d_in[0];
    const float* child_h = (const float*)d_in[1];
    const float* hsum    = (const float*)d_in[2];
    const float* W_ih    = (const float*)d_in[3];
    const float* b_ih    = (const float*)d_in[4];
    const float* W_fh    = (const float*)d_in[5];
    const float* b_fh    = (const float*)d_in[6];
    const float* W_uh    = (const float*)d_in[7];
    const float* b_uh    = (const float*)d_in[8];
    const float* W_oh    = (const float*)d_in[9];
    const float* b_oh    = (const float*)d_in[10];

    static bool attr_done = false;
    if (!attr_done) {
        cudaFuncSetAttribute(fgemm_kernel,
                             cudaFuncAttributeMaxDynamicSharedMemorySize, SMEM_TOTAL);
        attr_done = true;
    }

    prep_gates<<<GATE_BLOCKS + PREP_BLOCKS, 256>>>(child_h, W_fh, hsum,
                                                   W_ih, b_ih, W_uh, b_uh, W_oh, b_oh);

    dim3 grid(MEM_DIM / BN, N_CHILD / BM);   // (8, 128)
    fgemm_kernel<<<grid, THREADS, SMEM_TOTAL>>>(child_c, b_fh, (float*)d_out);
}

// round 11
// speedup vs baseline: 5.5315x; 1.0167x over previous
#include <cuda_runtime.h>
#include <cuda_fp16.h>
#include <math.h>
#include <stdint.h>

#define MEM_DIM 1024
#define N_CHILD 16384

#define BM 128
#define BN 128
#define BKH 32                     // K halves per pipeline stage
#define KITERS (MEM_DIM / BKH)     // 32
#define SAH 40                     // padded row stride in halves (80B)
#define THREADS 256
#define NSTAGE 5
#define STAGE_BYTES 20480          // (A 10240 + B 10240) per stage
#define RED_OFF (NSTAGE * STAGE_BYTES)          // 102400
#define FLAG_OFF (RED_OFF + 2 * BN * 4)         // 103424
#define SMEM_TOTAL (FLAG_OFF + 16)              // 103440
#define GRID_TOTAL ((MEM_DIM / BN) * (N_CHILD / BM))  // 1024

// ---- device scratch (no cudaMalloc allowed) ----
__device__ float  g_gates[3 * MEM_DIM];
__device__ float  g_fcsum[MEM_DIM];
__device__ unsigned int g_done;
__device__ __half g_h_h[(size_t)N_CHILD * MEM_DIM];   // fp16 child_h
__device__ __half g_w_h[(size_t)MEM_DIM * MEM_DIM];   // fp16 W_fh

// ---------------------------------------------------------------------------
__device__ __forceinline__ void ldm_x4(uint32_t* r, uint32_t addr) {
    asm volatile("ldmatrix.sync.aligned.m8n8.x4.shared.b16 {%0,%1,%2,%3}, [%4];"
                 : "=r"(r[0]), "=r"(r[1]), "=r"(r[2]), "=r"(r[3]) : "r"(addr));
}
__device__ __forceinline__ void mma_f16(float* d, const uint32_t* a, const uint32_t* b) {
    asm volatile(
        "mma.sync.aligned.m16n8k16.row.col.f32.f16.f16.f32 "
        "{%0,%1,%2,%3}, {%4,%5,%6,%7}, {%8,%9}, {%0,%1,%2,%3};\n"
        : "+f"(d[0]), "+f"(d[1]), "+f"(d[2]), "+f"(d[3])
        : "r"(a[0]), "r"(a[1]), "r"(a[2]), "r"(a[3]), "r"(b[0]), "r"(b[1]));
}
__device__ __forceinline__ void cpa16(uint32_t s, const void* g) {
    asm volatile("cp.async.cg.shared.global [%0], [%1], 16;\n" :: "r"(s), "l"(g));
}
__device__ __forceinline__ float sigmoidf_(float x) {
    return 1.0f / (1.0f + __expf(-x));
}

// ---------------------------------------------------------------------------
// Prep + gates fused.
// ---------------------------------------------------------------------------
#define GATE_BLOCKS 384
#define PREP_BLOCKS 2048

__global__ void prep_gates(const float* __restrict__ h, const float* __restrict__ w,
                           const float* __restrict__ hsum,
                           const float* __restrict__ W_ih, const float* __restrict__ b_ih,
                           const float* __restrict__ W_uh, const float* __restrict__ b_uh,
                           const float* __restrict__ W_oh, const float* __restrict__ b_oh) {
    if (blockIdx.x < GATE_BLOCKS) {
        if (blockIdx.x == 0) {
            for (int j = threadIdx.x; j < MEM_DIM; j += blockDim.x) g_fcsum[j] = 0.0f;
            if (threadIdx.x == 0) g_done = 0u;
        }
        int warp = (blockIdx.x * blockDim.x + threadIdx.x) >> 5;
        int lane = threadIdx.x & 31;
        if (warp >= 3 * MEM_DIM) return;
        int gate = warp / MEM_DIM;
        int row  = warp % MEM_DIM;
        const float* W = (gate == 0) ? W_ih : ((gate == 1) ? W_oh : W_uh);
        const float* b = (gate == 0) ? b_ih : ((gate == 1) ? b_oh : b_uh);
        const float4* h4 = (const float4*)hsum;
        const float4* w4 = (const float4*)(W + (size_t)row * MEM_DIM);
        float s = 0.0f;
#pragma unroll
        for (int idx = 0; idx < MEM_DIM / 128; idx++) {
            float4 hv = h4[lane + idx * 32];
            float4 wv = w4[lane + idx * 32];
            s += hv.x * wv.x + hv.y * wv.y + hv.z * wv.z + hv.w * wv.w;
        }
#pragma unroll
        for (int off = 16; off > 0; off >>= 1) s += __shfl_xor_sync(0xffffffffu, s, off);
        if (lane == 0) {
            float pre = s + b[row];
            g_gates[gate * MEM_DIM + row] = (gate == 2) ? tanhf(pre) : 1.0f / (1.0f + expf(-pre));
        }
        return;
    }

    const int64_t NH = (int64_t)N_CHILD * MEM_DIM / 4;
    const int64_t NW = (int64_t)MEM_DIM * MEM_DIM / 4;
    int64_t i0 = (int64_t)(blockIdx.x - GATE_BLOCKS) * blockDim.x + threadIdx.x;
    int64_t stride = (int64_t)PREP_BLOCKS * blockDim.x;
    const float4* h4 = (const float4*)h;
    __half2* ho = (__half2*)g_h_h;
    for (int64_t k = i0; k < NH; k += stride) {
        float4 v = h4[k];
        ho[2 * k]     = __floats2half2_rn(v.x, v.y);
        ho[2 * k + 1] = __floats2half2_rn(v.z, v.w);
    }
    const float4* w4 = (const float4*)w;
    __half2* wo = (__half2*)g_w_h;
    for (int64_t k = i0; k < NW; k += stride) {
        float4 v = w4[k];
        wo[2 * k]     = __floats2half2_rn(v.x, v.y);
        wo[2 * k + 1] = __floats2half2_rn(v.z, v.w);
    }
}

// ---------------------------------------------------------------------------
// Main GEMM: fp16 mma.m16n8k16, 5-stage cp.async ring, cross-iteration
// fragment software pipeline. Last CTA computes the final c/h output.
// ---------------------------------------------------------------------------
__global__ void __launch_bounds__(THREADS, 2)
fgemm_kernel(const float* __restrict__ child_c,
             const float* __restrict__ b_fh,
             float* __restrict__ out) {
    extern __shared__ __align__(128) uint8_t smem_raw[];
    float* red = (float*)(smem_raw + RED_OFF);              // [2][BN]
    unsigned int* flag = (unsigned int*)(smem_raw + FLAG_OFF);

    const int tid  = threadIdx.x;
    const int lane = tid & 31;
    const int warp = tid >> 5;
    const int wm   = warp & 1;
    const int wn   = warp >> 1;
    const int g    = lane >> 2;
    const int t    = lane & 3;
    const int m0   = blockIdx.y * BM;
    const int n0   = blockIdx.x * BN;

    float acc[4][4][4];
#pragma unroll
    for (int mt = 0; mt < 4; mt++)
#pragma unroll
        for (int nt = 0; nt < 4; nt++)
#pragma unroll
            for (int r = 0; r < 4; r++) acc[mt][nt][r] = 0.0f;

    const uint32_t sBase = (uint32_t)__cvta_generic_to_shared(smem_raw);
    const __half* gH = g_h_h + (size_t)m0 * MEM_DIM;
    const __half* gW = g_w_h + (size_t)n0 * MEM_DIM;

    auto prefetch = [&](int k0, int s) {
#pragma unroll
        for (int l = 0; l < 2; l++) {
            int idx = tid + l * 256;
            int row = idx >> 2;
            int c   = idx & 3;
            uint32_t so = sBase + (uint32_t)s * STAGE_BYTES + (uint32_t)(row * SAH + c * 8) * 2;
            cpa16(so, gH + (size_t)row * MEM_DIM + k0 + c * 8);
            cpa16(so + 10240u, gW + (size_t)row * MEM_DIM + k0 + c * 8);
        }
    };

    // ldmatrix lane-address components
    const int q  = lane >> 3;
    const int r8 = lane & 7;
    const int a_row = wm * 64 + (q & 1) * 8 + r8;
    const int a_col = (q >> 1) * 8;
    const int b_row = wn * 32 + (q >> 1) * 8 + r8;
    const int b_col = (q & 1) * 8;

    auto load_frag = [&](uint32_t af[4][4], uint32_t bf[2][4], int s, int kk) {
        uint32_t baseA = sBase + (uint32_t)s * STAGE_BYTES;
        uint32_t baseB = baseA + 10240u;
#pragma unroll
        for (int mt = 0; mt < 4; mt++)
            ldm_x4(af[mt], baseA + ((a_row + mt * 16) * SAH + a_col + kk) * 2);
#pragma unroll
        for (int p = 0; p < 2; p++)
            ldm_x4(bf[p], baseB + ((b_row + p * 16) * SAH + b_col + kk) * 2);
    };
    auto do_mma = [&](uint32_t af[4][4], uint32_t bf[2][4]) {
#pragma unroll
        for (int mt = 0; mt < 4; mt++)
#pragma unroll
            for (int nt = 0; nt < 4; nt++)
                mma_f16(acc[mt][nt], af[mt], &bf[nt >> 1][(nt & 1) * 2]);
    };

    // ---- prologue: fill stages 0..3 ----
#pragma unroll
    for (int s = 0; s < 4; s++) {
        prefetch(s * BKH, s);
        asm volatile("cp.async.commit_group;\n");
    }
    asm volatile("cp.async.wait_group 3;\n");   // stage 0 arrived
    __syncthreads();

    uint32_t afA[4][4], bfA[2][4], afB[4][4], bfB[2][4];
    load_frag(afA, bfA, 0, 0);                  // iter 0, ks=0

    int s_cur = 0, s_nxt = 1, s_pf = 4;
    for (int it = 0; it < KITERS; it++) {
        // ks=1 fragments of this stage, then MMAs for ks=0
        load_frag(afB, bfB, s_cur, 16);
        do_mma(afA, bfA);

        // stage it+1 guaranteed arrived after this wait (<=2 pending of it+2, it+3)
        asm volatile("cp.async.wait_group 2;\n");
        load_frag(afA, bfA, s_nxt, 0);          // next iter's ks=0 (harmless at tail)
        do_mma(afB, bfB);

        __syncthreads();                        // all warps done reading stage s_pf's slot
        if (it + 4 < KITERS) prefetch((it + 4) * BKH, s_pf);
        asm volatile("cp.async.commit_group;\n");

        s_cur = s_nxt;
        s_nxt = (s_nxt + 1 == NSTAGE) ? 0 : s_nxt + 1;
        s_pf  = (s_pf  + 1 == NSTAGE) ? 0 : s_pf  + 1;
    }

    // ---- Epilogue: f = sigmoid(y + b), colsum += f * child_c ----
    float b0v[4], b1v[4];
#pragma unroll
    for (int nt = 0; nt < 4; nt++) {
        float2 bb = *(const float2*)(b_fh + n0 + wn * 32 + nt * 8 + 2 * t);
        b0v[nt] = bb.x; b1v[nt] = bb.y;
    }

    float cs0[4] = {0.f, 0.f, 0.f, 0.f};
    float cs1[4] = {0.f, 0.f, 0.f, 0.f};
#pragma unroll
    for (int mt = 0; mt < 4; mt++) {
#pragma unroll
        for (int rr = 0; rr < 2; rr++) {
            int m = m0 + wm * 64 + mt * 16 + rr * 8 + g;
            const float* crow = child_c + (size_t)m * MEM_DIM + n0;
#pragma unroll
            for (int nt = 0; nt < 4; nt++) {
                int nc = wn * 32 + nt * 8 + 2 * t;
                float2 cc = *(const float2*)(crow + nc);
                float y0 = acc[mt][nt][rr * 2 + 0] + b0v[nt];
                float y1 = acc[mt][nt][rr * 2 + 1] + b1v[nt];
                cs0[nt] += cc.x * sigmoidf_(y0);
                cs1[nt] += cc.y * sigmoidf_(y1);
            }
        }
    }

#pragma unroll
    for (int off = 4; off < 32; off <<= 1) {
#pragma unroll
        for (int nt = 0; nt < 4; nt++) {
            cs0[nt] += __shfl_xor_sync(0xffffffffu, cs0[nt], off);
            cs1[nt] += __shfl_xor_sync(0xffffffffu, cs1[nt], off);
        }
    }
    if (g == 0) {
#pragma unroll
        for (int nt = 0; nt < 4; nt++) {
            int nc = wn * 32 + nt * 8 + 2 * t;
            red[wm * BN + nc]     = cs0[nt];
            red[wm * BN + nc + 1] = cs1[nt];
        }
    }
    __syncthreads();
    if (tid < BN) {
        atomicAdd(&g_fcsum[n0 + tid], red[tid] + red[BN + tid]);
    }

    // ---- Grid-completion: last CTA computes the final output ----
    __threadfence();
    __syncthreads();
    if (tid == 0) {
        unsigned int prev = atomicAdd(&g_done, 1u);
        *flag = (prev == GRID_TOTAL - 1u);
    }
    __syncthreads();
    if (*flag) {
        __threadfence();
        for (int j = tid; j < MEM_DIM; j += THREADS) {
            float gi = g_gates[j];
            float go = g_gates[MEM_DIM + j];
            float gu = g_gates[2 * MEM_DIM + j];
            float c  = gi * gu + g_fcsum[j];
            out[j]           = c;
            out[MEM_DIM + j] = go * tanhf(c);
        }
    }
}

// ---------------------------------------------------------------------------
extern "C" void kernel_launch(void* const* d_in, const int* in_sizes, int n_in,
                              void* d_out, int out_size) {
    const float* child_c = (const float*)d_in[0];
    const float* child_h = (const float*)d_in[1];
    const float* hsum    = (const float*)d_in[2];
    const float* W_ih    = (const float*)d_in[3];
    const float* b_ih    = (const float*)d_in[4];
    const float* W_fh    = (const float*)d_in[5];
    const float* b_fh    = (const float*)d_in[6];
    const float* W_uh    = (const float*)d_in[7];
    const float* b_uh    = (const float*)d_in[8];
    const float* W_oh    = (const float*)d_in[9];
    const float* b_oh    = (const float*)d_in[10];

    static bool attr_done = false;
    if (!attr_done) {
        cudaFuncSetAttribute(fgemm_kernel,
                             cudaFuncAttributeMaxDynamicSharedMemorySize, SMEM_TOTAL);
        attr_done = true;
    }

    prep_gates<<<GATE_BLOCKS + PREP_BLOCKS, 256>>>(child_h, W_fh, hsum,
                                                   W_ih, b_ih, W_uh, b_uh, W_oh, b_oh);

    dim3 grid(MEM_DIM / BN, N_CHILD / BM);   // (8, 128)
    fgemm_kernel<<<grid, THREADS, SMEM_TOTAL>>>(child_c, b_fh, (float*)d_out);
}

// round 13
// speedup vs baseline: 5.5444x; 1.0023x over previous
#include <cuda_runtime.h>
#include <cuda_fp16.h>
#include <math.h>
#include <stdint.h>

#define MEM_DIM 1024
#define N_CHILD 16384

#define BM 128
#define BN 64
#define BKH 32                     // K halves per pipeline stage
#define KITERS (MEM_DIM / BKH)     // 32
#define SAH 40                     // padded row stride in halves (80B)
#define THREADS 256
#define NSTAGE 4
#define A_BYTES 10240              // 128 * 40 * 2
#define B_BYTES 5120               // 64 * 40 * 2
#define STAGE_BYTES (A_BYTES + B_BYTES)          // 15360
#define RED_OFF (NSTAGE * STAGE_BYTES)           // 61440
#define FLAG_OFF (RED_OFF + 4 * BN * 4)          // 62464
#define SMEM_TOTAL (FLAG_OFF + 16)               // 62480
#define GRID_TOTAL ((MEM_DIM / BN) * (N_CHILD / BM))  // 2048

// ---- device scratch (no cudaMalloc allowed) ----
__device__ float  g_gates[3 * MEM_DIM];
__device__ float  g_fcsum[MEM_DIM];
__device__ unsigned int g_done;
__device__ __half g_h_h[(size_t)N_CHILD * MEM_DIM];   // fp16 child_h
__device__ __half g_w_h[(size_t)MEM_DIM * MEM_DIM];   // fp16 W_fh

// ---------------------------------------------------------------------------
__device__ __forceinline__ void ldm_x4(uint32_t* r, uint32_t addr) {
    asm volatile("ldmatrix.sync.aligned.m8n8.x4.shared.b16 {%0,%1,%2,%3}, [%4];"
                 : "=r"(r[0]), "=r"(r[1]), "=r"(r[2]), "=r"(r[3]) : "r"(addr));
}
__device__ __forceinline__ void mma_f16(float* d, const uint32_t* a, const uint32_t* b) {
    asm volatile(
        "mma.sync.aligned.m16n8k16.row.col.f32.f16.f16.f32 "
        "{%0,%1,%2,%3}, {%4,%5,%6,%7}, {%8,%9}, {%0,%1,%2,%3};\n"
        : "+f"(d[0]), "+f"(d[1]), "+f"(d[2]), "+f"(d[3])
        : "r"(a[0]), "r"(a[1]), "r"(a[2]), "r"(a[3]), "r"(b[0]), "r"(b[1]));
}
__device__ __forceinline__ void cpa16(uint32_t s, const void* g) {
    asm volatile("cp.async.cg.shared.global [%0], [%1], 16;\n" :: "r"(s), "l"(g));
}
__device__ __forceinline__ float sigmoidf_(float x) {
    return 1.0f / (1.0f + __expf(-x));
}

// ---------------------------------------------------------------------------
// Prep + gates fused: blocks [0,384) do the i/o/u matvecs; the rest convert
// child_h / W_fh to fp16. Block 0 also zeroes g_fcsum and g_done.
// ---------------------------------------------------------------------------
#define GATE_BLOCKS 384
#define PREP_BLOCKS 2048

__global__ void prep_gates(const float* __restrict__ h, const float* __restrict__ w,
                           const float* __restrict__ hsum,
                           const float* __restrict__ W_ih, const float* __restrict__ b_ih,
                           const float* __restrict__ W_uh, const float* __restrict__ b_uh,
                           const float* __restrict__ W_oh, const float* __restrict__ b_oh) {
    if (blockIdx.x < GATE_BLOCKS) {
        if (blockIdx.x == 0) {
            for (int j = threadIdx.x; j < MEM_DIM; j += blockDim.x) g_fcsum[j] = 0.0f;
            if (threadIdx.x == 0) g_done = 0u;
        }
        int warp = (blockIdx.x * blockDim.x + threadIdx.x) >> 5;
        int lane = threadIdx.x & 31;
        if (warp >= 3 * MEM_DIM) return;
        int gate = warp / MEM_DIM;
        int row  = warp % MEM_DIM;
        const float* W = (gate == 0) ? W_ih : ((gate == 1) ? W_oh : W_uh);
        const float* b = (gate == 0) ? b_ih : ((gate == 1) ? b_oh : b_uh);
        const float4* h4 = (const float4*)hsum;
        const float4* w4 = (const float4*)(W + (size_t)row * MEM_DIM);
        float s = 0.0f;
#pragma unroll
        for (int idx = 0; idx < MEM_DIM / 128; idx++) {
            float4 hv = h4[lane + idx * 32];
            float4 wv = w4[lane + idx * 32];
            s += hv.x * wv.x + hv.y * wv.y + hv.z * wv.z + hv.w * wv.w;
        }
#pragma unroll
        for (int off = 16; off > 0; off >>= 1) s += __shfl_xor_sync(0xffffffffu, s, off);
        if (lane == 0) {
            float pre = s + b[row];
            g_gates[gate * MEM_DIM + row] = (gate == 2) ? tanhf(pre) : 1.0f / (1.0f + expf(-pre));
        }
        return;
    }

    const int64_t NH = (int64_t)N_CHILD * MEM_DIM / 4;
    const int64_t NW = (int64_t)MEM_DIM * MEM_DIM / 4;
    int64_t i0 = (int64_t)(blockIdx.x - GATE_BLOCKS) * blockDim.x + threadIdx.x;
    int64_t stride = (int64_t)PREP_BLOCKS * blockDim.x;
    const float4* h4 = (const float4*)h;
    __half2* ho = (__half2*)g_h_h;
    for (int64_t k = i0; k < NH; k += stride) {
        float4 v = h4[k];
        ho[2 * k]     = __floats2half2_rn(v.x, v.y);
        ho[2 * k + 1] = __floats2half2_rn(v.z, v.w);
    }
    const float4* w4 = (const float4*)w;
    __half2* wo = (__half2*)g_w_h;
    for (int64_t k = i0; k < NW; k += stride) {
        float4 v = w4[k];
        wo[2 * k]     = __floats2half2_rn(v.x, v.y);
        wo[2 * k + 1] = __floats2half2_rn(v.z, v.w);
    }
}

// ---------------------------------------------------------------------------
// Main GEMM: fp16 mma.m16n8k16, 4-stage cp.async ring.
// CTA tile 128x64, 8 warps (4M x 2N), warp tile 32x32 -> low regs, 3 CTAs/SM.
// Last CTA computes the final c/h output.
// ---------------------------------------------------------------------------
__global__ void __launch_bounds__(THREADS, 3)
fgemm_kernel(const float* __restrict__ child_c,
             const float* __restrict__ b_fh,
             float* __restrict__ out) {
    extern __shared__ __align__(128) uint8_t smem_raw[];
    float* red = (float*)(smem_raw + RED_OFF);              // [4][BN]
    unsigned int* flag = (unsigned int*)(smem_raw + FLAG_OFF);

    const int tid  = threadIdx.x;
    const int lane = tid & 31;
    const int warp = tid >> 5;
    const int wm   = warp & 3;      // 0..3 -> 32 rows each
    const int wn   = warp >> 2;     // 0..1 -> 32 cols each
    const int g    = lane >> 2;     // 0..7
    const int t    = lane & 3;      // 0..3
    const int m0   = blockIdx.y * BM;
    const int n0   = blockIdx.x * BN;

    float acc[2][4][4];
#pragma unroll
    for (int mt = 0; mt < 2; mt++)
#pragma unroll
        for (int nt = 0; nt < 4; nt++)
#pragma unroll
            for (int r = 0; r < 4; r++) acc[mt][nt][r] = 0.0f;

    const uint32_t sBase = (uint32_t)__cvta_generic_to_shared(smem_raw);
    const __half* gH = g_h_h + (size_t)m0 * MEM_DIM;
    const __half* gW = g_w_h + (size_t)n0 * MEM_DIM;

    auto prefetch = [&](int k0, int s) {
        uint32_t sg = sBase + (uint32_t)s * STAGE_BYTES;
        // A: 128 rows x 4 chunks = 512 -> 2 per thread
#pragma unroll
        for (int l = 0; l < 2; l++) {
            int idx = tid + l * 256;
            int row = idx >> 2;
            int c   = idx & 3;
            cpa16(sg + (uint32_t)(row * SAH + c * 8) * 2,
                  gH + (size_t)row * MEM_DIM + k0 + c * 8);
        }
        // B: 64 rows x 4 chunks = 256 -> 1 per thread
        {
            int row = tid >> 2;
            int c   = tid & 3;
            cpa16(sg + A_BYTES + (uint32_t)(row * SAH + c * 8) * 2,
                  gW + (size_t)row * MEM_DIM + k0 + c * 8);
        }
    };

    // ldmatrix lane-address components
    const int q  = lane >> 3;
    const int r8 = lane & 7;
    const int a_row = wm * 32 + (q & 1) * 8 + r8;       // + mt*16
    const int a_col = (q >> 1) * 8;                     // + kk
    const int b_row = wn * 32 + (q >> 1) * 8 + r8;      // + p*16
    const int b_col = (q & 1) * 8;                      // + kk

    // ---- prologue: fill stages 0..2 ----
#pragma unroll
    for (int s = 0; s < 3; s++) {
        prefetch(s * BKH, s);
        asm volatile("cp.async.commit_group;\n");
    }

    for (int it = 0; it < KITERS; it++) {
        int s = it & 3;
        asm volatile("cp.async.wait_group 2;\n");   // stage it arrived
        __syncthreads();
        if (it + 3 < KITERS) prefetch((it + 3) * BKH, (it + 3) & 3);
        asm volatile("cp.async.commit_group;\n");

        uint32_t baseA = sBase + (uint32_t)s * STAGE_BYTES;
        uint32_t baseB = baseA + A_BYTES;
#pragma unroll
        for (int ks = 0; ks < 2; ks++) {
            const int kk = ks * 16;
            uint32_t af[2][4], bf[2][4];
#pragma unroll
            for (int mt = 0; mt < 2; mt++)
                ldm_x4(af[mt], baseA + ((a_row + mt * 16) * SAH + a_col + kk) * 2);
#pragma unroll
            for (int p = 0; p < 2; p++)
                ldm_x4(bf[p], baseB + ((b_row + p * 16) * SAH + b_col + kk) * 2);
#pragma unroll
            for (int mt = 0; mt < 2; mt++)
#pragma unroll
                for (int nt = 0; nt < 4; nt++)
                    mma_f16(acc[mt][nt], af[mt], &bf[nt >> 1][(nt & 1) * 2]);
        }
    }

    // ---- Epilogue: f = sigmoid(y + b), colsum += f * child_c ----
    float b0v[4], b1v[4];
#pragma unroll
    for (int nt = 0; nt < 4; nt++) {
        float2 bb = *(const float2*)(b_fh + n0 + wn * 32 + nt * 8 + 2 * t);
        b0v[nt] = bb.x; b1v[nt] = bb.y;
    }

    float cs0[4] = {0.f, 0.f, 0.f, 0.f};
    float cs1[4] = {0.f, 0.f, 0.f, 0.f};
#pragma unroll
    for (int mt = 0; mt < 2; mt++) {
#pragma unroll
        for (int rr = 0; rr < 2; rr++) {
            int m = m0 + wm * 32 + mt * 16 + rr * 8 + g;
            const float* crow = child_c + (size_t)m * MEM_DIM + n0;
#pragma unroll
            for (int nt = 0; nt < 4; nt++) {
                int nc = wn * 32 + nt * 8 + 2 * t;
                float2 cc = *(const float2*)(crow + nc);
                float y0 = acc[mt][nt][rr * 2 + 0] + b0v[nt];
                float y1 = acc[mt][nt][rr * 2 + 1] + b1v[nt];
                cs0[nt] += cc.x * sigmoidf_(y0);
                cs1[nt] += cc.y * sigmoidf_(y1);
            }
        }
    }

    // Reduce over the 8 row-groups (lanes differing in g): xor 4, 8, 16.
#pragma unroll
    for (int off = 4; off < 32; off <<= 1) {
#pragma unroll
        for (int nt = 0; nt < 4; nt++) {
            cs0[nt] += __shfl_xor_sync(0xffffffffu, cs0[nt], off);
            cs1[nt] += __shfl_xor_sync(0xffffffffu, cs1[nt], off);
        }
    }
    if (g == 0) {  // lanes 0..3 hold per-column sums for this warp
#pragma unroll
        for (int nt = 0; nt < 4; nt++) {
            int nc = wn * 32 + nt * 8 + 2 * t;
            red[wm * BN + nc]     = cs0[nt];
            red[wm * BN + nc + 1] = cs1[nt];
        }
    }
    __syncthreads();
    if (tid < BN) {
        atomicAdd(&g_fcsum[n0 + tid],
                  red[tid] + red[BN + tid] + red[2 * BN + tid] + red[3 * BN + tid]);
    }

    // ---- Grid-completion: last CTA computes the final output ----
    __threadfence();
    __syncthreads();
    if (tid == 0) {
        unsigned int prev = atomicAdd(&g_done, 1u);
        *flag = (prev == GRID_TOTAL - 1u);
    }
    __syncthreads();
    if (*flag) {
        __threadfence();
        for (int j = tid; j < MEM_DIM; j += THREADS) {
            float gi = g_gates[j];
            float go = g_gates[MEM_DIM + j];
            float gu = g_gates[2 * MEM_DIM + j];
            float c  = gi * gu + g_fcsum[j];
            out[j]           = c;
            out[MEM_DIM + j] = go * tanhf(c);
        }
    }
}

// ---------------------------------------------------------------------------
extern "C" void kernel_launch(void* const* d_in, const int* in_sizes, int n_in,
                              void* d_out, int out_size) {
    const float* child_c = (const float*)d_in[0];
    const float* child_h = (const float*)d_in[1];
    const float* hsum    = (const float*)d_in[2];
    const float* W_ih    = (const float*)d_in[3];
    const float* b_ih    = (const float*)d_in[4];
    const float* W_fh    = (const float*)d_in[5];
    const float* b_fh    = (const float*)d_in[6];
    const float* W_uh    = (const float*)d_in[7];
    const float* b_uh    = (const float*)d_in[8];
    const float* W_oh    = (const float*)d_in[9];
    const float* b_oh    = (const float*)d_in[10];

    static bool attr_done = false;
    if (!attr_done) {
        cudaFuncSetAttribute(fgemm_kernel,
                             cudaFuncAttributeMaxDynamicSharedMemorySize, SMEM_TOTAL);
        attr_done = true;
    }

    prep_gates<<<GATE_BLOCKS + PREP_BLOCKS, 256>>>(child_h, W_fh, hsum,
                                                   W_ih, b_ih, W_uh, b_uh, W_oh, b_oh);

    dim3 grid(MEM_DIM / BN, N_CHILD / BM);   // (16, 128)
    fgemm_kernel<<<grid, THREADS, SMEM_TOTAL>>>(child_c, b_fh, (float*)d_out);
}